// round 3
// baseline (speedup 1.0000x reference)
#include <cuda_runtime.h>

// SPP: out = concat(x, pool5(x), pool9(x), pool13(x)) along channels.
// pool9 = pool5(pool5(x)), pool13 = pool5(pool9); separable 1-D passes.
// R3: compact float2 halo arrays for the h-pass (halve its LDS bytes),
//     streaming cache hints on gmem (no reuse either direction).

#define NPLANES   8192      // 16 * 512
#define PLANE_F4  1024      // 64*64 / 4 (64 rows x 16 float4)
#define THREADS   256

__device__ __forceinline__ float4 v4max(float4 a, float4 b) {
    return make_float4(fmaxf(a.x, b.x), fmaxf(a.y, b.y),
                       fmaxf(a.z, b.z), fmaxf(a.w, b.w));
}

// 5-wide horizontal max: window [p.x p.y | c.x c.y c.z c.w | n.x n.y]
// where p = left neighbor's (z,w), n = right neighbor's (x,y).
__device__ __forceinline__ float4 hmax5(float2 p, float4 c, float2 n) {
    float m01 = fmaxf(c.x, c.y);
    float m23 = fmaxf(c.z, c.w);
    float m0123 = fmaxf(m01, m23);
    float4 o;
    o.x = fmaxf(fmaxf(p.x, p.y), fmaxf(m01, c.z));
    o.y = fmaxf(p.y, m0123);
    o.z = fmaxf(m0123, n.x);
    o.w = fmaxf(fmaxf(c.y, m23), fmaxf(n.x, n.y));
    return o;
}

__global__ __launch_bounds__(THREADS)
void spp_kernel(const float4* __restrict__ in, float4* __restrict__ out) {
    __shared__ float2 Lh[PLANE_F4];  // v.zw  (left-halo feed for right neighbor)
    __shared__ float2 Rh[PLANE_F4];  // v.xy  (right-halo feed for left neighbor)
    __shared__ float4 B[PLANE_F4];   // h-pass results (neighbor-row exchange)

    const float NEG = __int_as_float(0xff800000);  // -inf
    const float4 NEG4 = make_float4(NEG, NEG, NEG, NEG);
    const float2 NEG2 = make_float2(NEG, NEG);

    const int plane = blockIdx.x;           // n*512 + c
    const int n = plane >> 9;
    const int c = plane & 511;
    const int xg = threadIdx.x & 15;        // float4 column 0..15
    const int yg = threadIdx.x >> 4;        // row-strip 0..15 (rows 4*yg..4*yg+3)
    const int base = ((yg << 2) << 4) + xg; // index of row 4*yg, column xg

    const float4* src = in + (size_t)plane * PLANE_F4;
    float4* out0 = out + ((size_t)n * 2048 + c) * PLANE_F4;

    // ---- load strip + write copy section + publish halos ----
    float4 v[4];
    #pragma unroll
    for (int r = 0; r < 4; r++) {
        int t = base + (r << 4);
        v[r] = __ldcs(&src[t]);
        Lh[t] = make_float2(v[r].z, v[r].w);
        Rh[t] = make_float2(v[r].x, v[r].y);
        __stcs(&out0[t], v[r]);
    }
    __syncthreads();

    // ---- three cascaded pool5 stages ----
    #pragma unroll
    for (int pool = 0; pool < 3; pool++) {
        // horizontal pass: center from regs, neighbor halves from Lh/Rh
        float4 h[4];
        #pragma unroll
        for (int r = 0; r < 4; r++) {
            int t = base + (r << 4);
            float2 p  = (xg > 0)  ? Lh[t - 1] : NEG2;
            float2 nx = (xg < 15) ? Rh[t + 1] : NEG2;
            h[r] = hmax5(p, v[r], nx);
            B[t] = h[r];
        }
        __syncthreads();

        // vertical pass: my 4 h-rows in regs + 2 above + 2 below from B
        float4 u0 = (yg > 0)  ? B[base - 32] : NEG4;   // row 4yg-2
        float4 u1 = (yg > 0)  ? B[base - 16] : NEG4;   // row 4yg-1
        float4 d0 = (yg < 15) ? B[base + 64] : NEG4;   // row 4yg+4
        float4 d1 = (yg < 15) ? B[base + 80] : NEG4;   // row 4yg+5

        float4 m12 = v4max(h[1], h[2]);                // shared subexpression
        v[0] = v4max(v4max(u0, u1), v4max(h[0], m12));
        v[1] = v4max(v4max(u1, h[0]), v4max(m12, h[3]));
        v[2] = v4max(v4max(h[0], m12), v4max(h[3], d0));
        v[3] = v4max(v4max(m12, h[3]), v4max(d0, d1));

        float4* outs = out0 + (size_t)(pool + 1) * 512 * PLANE_F4;
        #pragma unroll
        for (int r = 0; r < 4; r++) {
            int t = base + (r << 4);
            if (pool < 2) {
                Lh[t] = make_float2(v[r].z, v[r].w);
                Rh[t] = make_float2(v[r].x, v[r].y);
            }
            __stcs(&outs[t], v[r]);
        }
        if (pool < 2) __syncthreads();
    }
}

extern "C" void kernel_launch(void* const* d_in, const int* in_sizes, int n_in,
                              void* d_out, int out_size) {
    const float4* x = (const float4*)d_in[0];
    float4* out = (float4*)d_out;
    spp_kernel<<<NPLANES, THREADS>>>(x, out);
}

// round 4
// speedup vs baseline: 1.0802x; 1.0802x over previous
#include <cuda_runtime.h>

// SPP: out = concat(x, pool5(x), pool9(x), pool13(x)) along channels.
// pool9 = pool5(pool5(x)), pool13 = pool5(pool9); separable 1-D passes.
// R4: single 16KB smem buffer (A/B merged, +2 syncs per pass) ->
//     5 blocks/SM instead of 3 for latency hiding. No cache hints (R3 regression).

#define NPLANES   8192      // 16 * 512
#define PLANE_F4  1024      // 64*64 / 4 (64 rows x 16 float4)
#define THREADS   256

__device__ __forceinline__ float4 v4max(float4 a, float4 b) {
    return make_float4(fmaxf(a.x, b.x), fmaxf(a.y, b.y),
                       fmaxf(a.z, b.z), fmaxf(a.w, b.w));
}

// 5-wide horizontal max over [p.z p.w | c.x c.y c.z c.w | n.x n.y]
__device__ __forceinline__ float4 hmax5(float4 p, float4 c, float4 n) {
    float m01 = fmaxf(c.x, c.y);
    float m23 = fmaxf(c.z, c.w);
    float m0123 = fmaxf(m01, m23);
    float4 o;
    o.x = fmaxf(fmaxf(p.z, p.w), fmaxf(m01, c.z));
    o.y = fmaxf(p.w, m0123);
    o.z = fmaxf(m0123, n.x);
    o.w = fmaxf(fmaxf(c.y, m23), fmaxf(n.x, n.y));
    return o;
}

__global__ __launch_bounds__(THREADS, 5)
void spp_kernel(const float4* __restrict__ in, float4* __restrict__ out) {
    __shared__ float4 S[PLANE_F4];  // shared by h- and v-exchange (time-multiplexed)

    const float NEG = __int_as_float(0xff800000);  // -inf
    const float4 NEG4 = make_float4(NEG, NEG, NEG, NEG);

    const int plane = blockIdx.x;           // n*512 + c
    const int n = plane >> 9;
    const int c = plane & 511;
    const int xg = threadIdx.x & 15;        // float4 column 0..15
    const int yg = threadIdx.x >> 4;        // row-strip 0..15 (rows 4*yg..4*yg+3)
    const int base = ((yg << 2) << 4) + xg; // index of row 4*yg, column xg

    const float4* src = in + (size_t)plane * PLANE_F4;
    float4* out0 = out + ((size_t)n * 2048 + c) * PLANE_F4;

    // ---- load strip + write copy section ----
    float4 v[4];
    #pragma unroll
    for (int r = 0; r < 4; r++) {
        int t = base + (r << 4);
        v[r] = src[t];
        S[t] = v[r];
        out0[t] = v[r];
    }
    __syncthreads();

    // ---- three cascaded pool5 stages ----
    #pragma unroll
    for (int pool = 0; pool < 3; pool++) {
        // horizontal pass: center from regs, neighbor columns from S (= v-plane)
        float4 h[4];
        #pragma unroll
        for (int r = 0; r < 4; r++) {
            int t = base + (r << 4);
            float4 p  = (xg > 0)  ? S[t - 1] : NEG4;
            float4 nx = (xg < 15) ? S[t + 1] : NEG4;
            h[r] = hmax5(p, v[r], nx);
        }
        __syncthreads();                     // everyone's h-pass reads done
        #pragma unroll
        for (int r = 0; r < 4; r++) S[base + (r << 4)] = h[r];
        __syncthreads();                     // h-results visible

        // vertical pass: my 4 h-rows in regs + 2 above + 2 below from S
        float4 u0 = (yg > 0)  ? S[base - 32] : NEG4;   // row 4yg-2
        float4 u1 = (yg > 0)  ? S[base - 16] : NEG4;   // row 4yg-1
        float4 d0 = (yg < 15) ? S[base + 64] : NEG4;   // row 4yg+4
        float4 d1 = (yg < 15) ? S[base + 80] : NEG4;   // row 4yg+5

        float4 m12 = v4max(h[1], h[2]);                // shared subexpression
        v[0] = v4max(v4max(u0, u1), v4max(h[0], m12));
        v[1] = v4max(v4max(u1, h[0]), v4max(m12, h[3]));
        v[2] = v4max(v4max(h[0], m12), v4max(h[3], d0));
        v[3] = v4max(v4max(m12, h[3]), v4max(d0, d1));

        float4* outs = out0 + (size_t)(pool + 1) * 512 * PLANE_F4;
        #pragma unroll
        for (int r = 0; r < 4; r++) outs[base + (r << 4)] = v[r];

        if (pool < 2) {
            __syncthreads();                 // v-pass reads of S done
            #pragma unroll
            for (int r = 0; r < 4; r++) S[base + (r << 4)] = v[r];
            __syncthreads();                 // v-plane visible for next h-pass
        }
    }
}

extern "C" void kernel_launch(void* const* d_in, const int* in_sizes, int n_in,
                              void* d_out, int out_size) {
    const float4* x = (const float4*)d_in[0];
    float4* out = (float4*)d_out;
    spp_kernel<<<NPLANES, THREADS>>>(x, out);
}

// round 5
// speedup vs baseline: 1.1062x; 1.0240x over previous
#include <cuda_runtime.h>
#include <cstdint>

// SPP: out = concat(x, pool5(x), pool9(x), pool13(x)) along channels.
// pool9 = pool5(pool5(x)), pool13 = pool5(pool9); separable 1-D passes.
// R5: all gmem writes via cp.async.bulk (16KB smem->gmem per section),
//     double-buffered smem pipelined with bulk_group wait<1>.

#define NPLANES   8192      // 16 * 512
#define PLANE_F4  1024      // 64*64 / 4 (64 rows x 16 float4)
#define PLANE_BYTES 16384
#define THREADS   256

__device__ __forceinline__ uint32_t smem_u32(const void* p) {
    return (uint32_t)__cvta_generic_to_shared(p);
}

__device__ __forceinline__ void bulk_store(void* gdst, uint32_t ssrc) {
    asm volatile(
        "cp.async.bulk.global.shared::cta.bulk_group [%0], [%1], %2;"
        :: "l"(gdst), "r"(ssrc), "n"(PLANE_BYTES) : "memory");
    asm volatile("cp.async.bulk.commit_group;" ::: "memory");
}

__device__ __forceinline__ void fence_async() {
    asm volatile("fence.proxy.async.shared::cta;" ::: "memory");
}

template <int N>
__device__ __forceinline__ void bulk_wait() {
    asm volatile("cp.async.bulk.wait_group %0;" :: "n"(N) : "memory");
}

__device__ __forceinline__ float4 v4max(float4 a, float4 b) {
    return make_float4(fmaxf(a.x, b.x), fmaxf(a.y, b.y),
                       fmaxf(a.z, b.z), fmaxf(a.w, b.w));
}

// 5-wide horizontal max over [p.z p.w | c.x c.y c.z c.w | n.x n.y]
__device__ __forceinline__ float4 hmax5(float4 p, float4 c, float4 n) {
    float m01 = fmaxf(c.x, c.y);
    float m23 = fmaxf(c.z, c.w);
    float m0123 = fmaxf(m01, m23);
    float4 o;
    o.x = fmaxf(fmaxf(p.z, p.w), fmaxf(m01, c.z));
    o.y = fmaxf(p.w, m0123);
    o.z = fmaxf(m0123, n.x);
    o.w = fmaxf(fmaxf(c.y, m23), fmaxf(n.x, n.y));
    return o;
}

__global__ __launch_bounds__(THREADS, 5)
void spp_kernel(const float4* __restrict__ in, float4* __restrict__ out) {
    __shared__ float4 S0[PLANE_F4];
    __shared__ float4 S1[PLANE_F4];

    const float NEG = __int_as_float(0xff800000);  // -inf
    const float4 NEG4 = make_float4(NEG, NEG, NEG, NEG);

    const int plane = blockIdx.x;           // n*512 + c
    const int n = plane >> 9;
    const int c = plane & 511;
    const int tid = threadIdx.x;
    const int xg = tid & 15;                // float4 column 0..15
    const int yg = tid >> 4;                // row-strip 0..15 (rows 4*yg..4*yg+3)
    const int base = ((yg << 2) << 4) + xg; // index of row 4*yg, column xg

    const float4* src = in + (size_t)plane * PLANE_F4;
    float4* out0 = out + ((size_t)n * 2048 + c) * PLANE_F4;

    // ---- load strip into S0; copy section via bulk store from S0 ----
    float4 v[4];
    #pragma unroll
    for (int r = 0; r < 4; r++) {
        int t = base + (r << 4);
        v[r] = src[t];
        S0[t] = v[r];
    }
    __syncthreads();
    if (tid == 0) {
        fence_async();
        bulk_store(out0, smem_u32(S0));     // W_copy (reads S0)
    }

    float4* cur = S0;                       // holds current v-plane
    float4* nxt = S1;

    // ---- three cascaded pool5 stages ----
    #pragma unroll
    for (int pool = 0; pool < 3; pool++) {
        // horizontal pass: center from regs, neighbor columns from cur
        float4 h[4];
        #pragma unroll
        for (int r = 0; r < 4; r++) {
            int t = base + (r << 4);
            float4 p  = (xg > 0)  ? cur[t - 1] : NEG4;
            float4 nx = (xg < 15) ? cur[t + 1] : NEG4;
            h[r] = hmax5(p, v[r], nx);
        }
        // before overwriting nxt: its previous bulk store (2 groups back) must be done
        if (tid == 0) bulk_wait<1>();
        __syncthreads();
        #pragma unroll
        for (int r = 0; r < 4; r++) nxt[base + (r << 4)] = h[r];
        __syncthreads();

        // vertical pass: my 4 h-rows in regs + 2 above + 2 below from nxt
        float4 u0 = (yg > 0)  ? nxt[base - 32] : NEG4;  // row 4yg-2
        float4 u1 = (yg > 0)  ? nxt[base - 16] : NEG4;  // row 4yg-1
        float4 d0 = (yg < 15) ? nxt[base + 64] : NEG4;  // row 4yg+4
        float4 d1 = (yg < 15) ? nxt[base + 80] : NEG4;  // row 4yg+5

        float4 m12 = v4max(h[1], h[2]);                 // shared subexpression
        v[0] = v4max(v4max(u0, u1), v4max(h[0], m12));
        v[1] = v4max(v4max(u1, h[0]), v4max(m12, h[3]));
        v[2] = v4max(v4max(h[0], m12), v4max(h[3], d0));
        v[3] = v4max(v4max(m12, h[3]), v4max(d0, d1));

        __syncthreads();                    // all v-pass reads of nxt done
        #pragma unroll
        for (int r = 0; r < 4; r++) nxt[base + (r << 4)] = v[r];
        __syncthreads();                    // v-plane complete in nxt
        if (tid == 0) {
            fence_async();
            bulk_store(out0 + (size_t)(pool + 1) * 512 * PLANE_F4, smem_u32(nxt));
        }
        // swap roles: nxt (now v-plane) becomes cur
        float4* tmp = cur; cur = nxt; nxt = tmp;
    }

    // drain remaining bulk stores before CTA exit
    if (tid == 0) bulk_wait<0>();
}

extern "C" void kernel_launch(void* const* d_in, const int* in_sizes, int n_in,
                              void* d_out, int out_size) {
    const float4* x = (const float4*)d_in[0];
    float4* out = (float4*)d_out;
    spp_kernel<<<NPLANES, THREADS>>>(x, out);
}